// round 4
// baseline (speedup 1.0000x reference)
#include <cuda_runtime.h>
#include <cuda_bf16.h>
#include <cstdint>

// Problem constants (fixed shapes)
#define B_SZ   256
#define T_SZ   512
#define EMB    128
#define HID    256
#define NCLS   32000

// Scratch: h0 at last timestep, stored bf16 for tensor-core GEMM
__device__ __nv_bfloat16 g_h0[B_SZ * HID];

// ---------------------------------------------------------------------------
// Kernel 1: h0_last[b, h] for the 256 last-timestep tokens.
// Grid (4, 32): x = hidden split (64 cols), y = batch group (8 rows).
// 256 threads = 64 hidden x 4 batch-subsets x 2 rows each.
// ---------------------------------------------------------------------------
__global__ void __launch_bounds__(256) lstm_h0_kernel(
    const int* __restrict__ X, const float* __restrict__ C_table,
    const float* __restrict__ U_i, const float* __restrict__ b_i,
    const float* __restrict__ U_c, const float* __restrict__ b_c,
    const float* __restrict__ U_o, const float* __restrict__ b_o)
{
    __shared__ float E_s[8][EMB];
    const int tid = threadIdx.x;
    const int b0  = blockIdx.y * 8;

    // Gather last-timestep embeddings for the 8 batch rows of this block
    for (int i = tid; i < 8 * EMB; i += 256) {
        int b = i >> 7;
        int e = i & (EMB - 1);
        int tok = X[(b0 + b) * T_SZ + (T_SZ - 1)];
        E_s[b][e] = C_table[tok * EMB + e];
    }
    __syncthreads();

    const int h    = blockIdx.x * 64 + (tid & 63);
    const int bsub = tid >> 6;           // 0..3 -> rows bsub*2, bsub*2+1
    const int r0   = bsub * 2;

    float ai[2], ag[2], ao[2];
    const float bi = b_i[h], bc = b_c[h], bo = b_o[h];
#pragma unroll
    for (int r = 0; r < 2; r++) { ai[r] = bi; ag[r] = bc; ao[r] = bo; }

#pragma unroll 4
    for (int e = 0; e < EMB; e++) {
        float ui = U_i[e * HID + h];
        float uc = U_c[e * HID + h];
        float uo = U_o[e * HID + h];
#pragma unroll
        for (int r = 0; r < 2; r++) {
            float ev = E_s[r0 + r][e];
            ai[r] = fmaf(ev, ui, ai[r]);
            ag[r] = fmaf(ev, uc, ag[r]);
            ao[r] = fmaf(ev, uo, ao[r]);
        }
    }

#pragma unroll
    for (int r = 0; r < 2; r++) {
        float i0 = 1.0f / (1.0f + __expf(-ai[r]));
        float g0 = tanhf(ag[r]);
        float o0 = 1.0f / (1.0f + __expf(-ao[r]));
        float c0 = i0 * g0;
        float h0 = o0 * tanhf(c0);
        g_h0[(b0 + r0 + r) * HID + h] = __float2bfloat16(h0);
    }
}

// ---------------------------------------------------------------------------
// Kernel 2: logits[256, 32000] = h0[256,256] @ W_w[32000,256]^T + b_out
// Plain pipelined bf16 mma.sync GEMM.
//   CTA tile: M=128 x N=128, K=256. grid = (250, 2), 256 threads, 2 CTAs/SM.
//   A (h0 half) bf16 resident in smem (stride 264 -> full 256-elem rows!).
//   B streamed fp32 via cp.async, K-chunks of 32, double-buffered
//   (wait_group 1; issue chunk c+2 after computing chunk c).
//   A fragments via ldmatrix.x4 (stride 528B -> conflict-free);
//   B fragments LDS.64 with BSTR=40 (8*gr bank spread -> conflict-free),
//   fp32->bf16 converted at fragment-load time.
// ---------------------------------------------------------------------------
#define BM      128
#define BN      128
#define ASTR    264              // A_s row stride in bf16 (528B): >= 256 + pad
#define CHUNK_K 32
#define NCHUNK  (HID / CHUNK_K)  // 8
#define BSTR    40               // B_s row stride in fp32 (160B, 16B aligned)
#define BBUF    (BN * BSTR)      // one B buffer, in floats (5120)

__device__ __forceinline__ void cp16(void* dst_smem, const void* src) {
    uint32_t d = (uint32_t)__cvta_generic_to_shared(dst_smem);
    asm volatile("cp.async.cg.shared.global [%0], [%1], 16;" :: "r"(d), "l"(src));
}
__device__ __forceinline__ void cp_commit() {
    asm volatile("cp.async.commit_group;" ::: "memory");
}
__device__ __forceinline__ void cp_wait1() {
    asm volatile("cp.async.wait_group 1;" ::: "memory");
}

__global__ void __launch_bounds__(256, 2) logits_kernel(
    const float* __restrict__ W_w, const float* __restrict__ b_out,
    float* __restrict__ out)
{
    extern __shared__ char smem_raw[];
    __nv_bfloat16* A_s = (__nv_bfloat16*)smem_raw;              // [128][ASTR]
    float*         B_s = (float*)(smem_raw + BM * ASTR * 2);    // 2*[128][BSTR]

    const int tid = threadIdx.x;
    const int n0  = blockIdx.x * BN;
    const int m0  = blockIdx.y * BM;

    // --- issue A load: g_h0 rows [m0, m0+128) (64KB) in 16B segments ---
    {
        const char* src = (const char*)(g_h0 + (size_t)m0 * HID);
#pragma unroll
        for (int k = 0; k < 16; k++) {
            int idx = tid + k * 256;       // 4096 segs (128 rows x 32 segs)
            int row = idx >> 5;
            int seg = idx & 31;            // 32 segs * 16B = 512B = 256 bf16
            cp16((char*)A_s + row * (ASTR * 2) + seg * 16,
                 src + row * (HID * 2) + seg * 16);
        }
    }
    // --- issue chunk 0 into buf 0, commit with A (group g0) ---
#pragma unroll
    for (int k = 0; k < 4; k++) {
        int idx = tid + k * 256;           // 1024 segs (128 rows x 8 segs)
        int row = idx >> 3;
        int seg = idx & 7;                 // 8 segs * 16B = 128B = 32 floats
        cp16(B_s + row * BSTR + seg * 4,
             W_w + (size_t)(n0 + row) * HID + seg * 4);
    }
    cp_commit();
    // --- issue chunk 1 into buf 1 (group g1) ---
#pragma unroll
    for (int k = 0; k < 4; k++) {
        int idx = tid + k * 256;
        int row = idx >> 3;
        int seg = idx & 7;
        cp16(B_s + BBUF + row * BSTR + seg * 4,
             W_w + (size_t)(n0 + row) * HID + CHUNK_K + seg * 4);
    }
    cp_commit();

    const int wid  = tid >> 5;
    const int lane = tid & 31;
    const int wm   = wid >> 2;      // 0..1 -> M offset wm*64
    const int wn   = wid & 3;       // 0..3 -> N offset wn*32
    const int gr   = lane >> 2;
    const int tig  = lane & 3;
    // ldmatrix lane address components (within A_s):
    const int lm_row = (lane & 15);        // row within 16
    const int lm_col = (lane >> 4) << 3;   // 0 or 8 (k-halves)

    float acc[4][4][4];
#pragma unroll
    for (int mi = 0; mi < 4; mi++)
#pragma unroll
        for (int ni = 0; ni < 4; ni++)
#pragma unroll
            for (int r = 0; r < 4; r++) acc[mi][ni][r] = 0.0f;

#pragma unroll
    for (int c = 0; c < NCHUNK; c++) {
        cp_wait1();        // chunk c (and A on first iter) complete
        __syncthreads();

        // ---- compute 2 kk steps of chunk c from buf c&1 ----
        const float* Bb = B_s + (c & 1) * BBUF;
#pragma unroll
        for (int kkl = 0; kkl < CHUNK_K / 16; kkl++) {
            const int kbg = c * CHUNK_K + kkl * 16;   // global K offset (A)
            const int kbl = kkl * 16;                 // local K offset (B)
            uint32_t a[4][4];
#pragma unroll
            for (int mi = 0; mi < 4; mi++) {
                uint32_t addr = (uint32_t)__cvta_generic_to_shared(
                    &A_s[(wm * 64 + mi * 16 + lm_row) * ASTR + kbg + lm_col]);
                asm volatile(
                    "ldmatrix.sync.aligned.m8n8.x4.shared.b16 {%0,%1,%2,%3}, [%4];"
                    : "=r"(a[mi][0]), "=r"(a[mi][1]), "=r"(a[mi][2]), "=r"(a[mi][3])
                    : "r"(addr));
            }
            uint32_t bf[4][2];
#pragma unroll
            for (int ni = 0; ni < 4; ni++) {
                const float* p =
                    Bb + (wn * 32 + ni * 8 + gr) * BSTR + kbl + tig * 2;
                float2 f0 = *(const float2*)(p);
                float2 f1 = *(const float2*)(p + 8);
                __nv_bfloat162 p0 = __floats2bfloat162_rn(f0.x, f0.y);
                __nv_bfloat162 p1 = __floats2bfloat162_rn(f1.x, f1.y);
                bf[ni][0] = *(const uint32_t*)&p0;
                bf[ni][1] = *(const uint32_t*)&p1;
            }
#pragma unroll
            for (int mi = 0; mi < 4; mi++) {
#pragma unroll
                for (int ni = 0; ni < 4; ni++) {
                    asm volatile(
                        "mma.sync.aligned.m16n8k16.row.col.f32.bf16.bf16.f32 "
                        "{%0,%1,%2,%3}, {%4,%5,%6,%7}, {%8,%9}, {%0,%1,%2,%3};"
                        : "+f"(acc[mi][ni][0]), "+f"(acc[mi][ni][1]),
                          "+f"(acc[mi][ni][2]), "+f"(acc[mi][ni][3])
                        : "r"(a[mi][0]), "r"(a[mi][1]), "r"(a[mi][2]), "r"(a[mi][3]),
                          "r"(bf[ni][0]), "r"(bf[ni][1]));
                }
            }
        }
        __syncthreads();   // all reads of buf c&1 done before it is re-filled

        // ---- issue chunk c+2 into buf c&1 (now free) ----
        if (c + 2 < NCHUNK) {
            float* dst = B_s + (c & 1) * BBUF;
            const float* src = W_w + (size_t)n0 * HID + (c + 2) * CHUNK_K;
#pragma unroll
            for (int k = 0; k < 4; k++) {
                int idx = tid + k * 256;
                int row = idx >> 3;
                int seg = idx & 7;
                cp16(dst + row * BSTR + seg * 4,
                     src + (size_t)row * HID + seg * 4);
            }
        }
        cp_commit();       // unconditional: keeps wait_group numbering forcing
    }

    // ---- epilogue: add b_out, fp32 float2 stores ----
    float bo0[4], bo1[4];
#pragma unroll
    for (int ni = 0; ni < 4; ni++) {
        int col = n0 + wn * 32 + ni * 8 + tig * 2;
        bo0[ni] = b_out[col];
        bo1[ni] = b_out[col + 1];
    }
#pragma unroll
    for (int mi = 0; mi < 4; mi++) {
        int row = m0 + wm * 64 + mi * 16 + gr;
#pragma unroll
        for (int ni = 0; ni < 4; ni++) {
            int col = n0 + wn * 32 + ni * 8 + tig * 2;
            float2 v0 = make_float2(acc[mi][ni][0] + bo0[ni],
                                    acc[mi][ni][1] + bo1[ni]);
            float2 v1 = make_float2(acc[mi][ni][2] + bo0[ni],
                                    acc[mi][ni][3] + bo1[ni]);
            *(float2*)(&out[(size_t)row * NCLS + col])       = v0;
            *(float2*)(&out[(size_t)(row + 8) * NCLS + col]) = v1;
        }
    }
}

// ---------------------------------------------------------------------------
// Launcher
// Input order: 0=X 1=C_table 2=U_i 3=V_i 4=b_i 5=U_f 6=V_f 7=b_f
//  8=U_c 9=V_c 10=b_c 11=U_o 12=V_o 13=b_o 14..25=layer1 (unused) 26=W_w 27=b_out
// ---------------------------------------------------------------------------
extern "C" void kernel_launch(void* const* d_in, const int* in_sizes, int n_in,
                              void* d_out, int out_size)
{
    const int*   X       = (const int*)d_in[0];
    const float* C_table = (const float*)d_in[1];
    const float* U_i     = (const float*)d_in[2];
    const float* b_i     = (const float*)d_in[4];
    const float* U_c     = (const float*)d_in[8];
    const float* b_c     = (const float*)d_in[10];
    const float* U_o     = (const float*)d_in[11];
    const float* b_o     = (const float*)d_in[13];
    const float* W_w     = (const float*)d_in[26];
    const float* b_out   = (const float*)d_in[27];
    float* out = (float*)d_out;

    dim3 grid1(4, 32);   // 128 blocks: 4 hidden splits x 32 batch groups
    lstm_h0_kernel<<<grid1, 256>>>(X, C_table, U_i, b_i, U_c, b_c, U_o, b_o);

    const int smem_bytes = BM * ASTR * 2 + 2 * BBUF * (int)sizeof(float); // 108544
    cudaFuncSetAttribute(logits_kernel,
                         cudaFuncAttributeMaxDynamicSharedMemorySize, smem_bytes);
    dim3 grid2(NCLS / BN, B_SZ / BM);   // (250, 2)
    logits_kernel<<<grid2, 256, smem_bytes>>>(W_w, b_out, out);
}